// round 6
// baseline (speedup 1.0000x reference)
#include <cuda_runtime.h>
#include <cuda_bf16.h>
#include <math.h>
#include <stdint.h>

// Problem constants
#define T_TOK 2048
#define D_DIM 1024
#define F_DIM 4096
#define E_EXP 8
#define K_TOP 2
#define NENT  (T_TOK * K_TOP)

// Tensor-core gemm1 tiling
#define BM 128
#define BN 128
#define BKS 32
#define ASTRIDE 40      // 80B row stride in smem

// SIMT gemm2 tiling (round-1 verified)
#define SBM 64
#define SBN 64
#define SBK 16

// ---------------------------------------------------------------------------
// Scratch
__device__ float g_h[(size_t)NENT * F_DIM];   // 64 MB fp32
__device__ int   g_list[E_EXP * T_TOK];
__device__ float g_wts[NENT];
__device__ int   g_cnt[E_EXP];
__device__ int   g_top1[E_EXP];
__device__ float g_psum[E_EXP];

// ---------------------------------------------------------------------------
__global__ void zero_kernel(float* out, int out_size) {
    int stride = gridDim.x * blockDim.x;
    for (int i = blockIdx.x * blockDim.x + threadIdx.x; i < out_size; i += stride)
        out[i] = 0.0f;
    if (blockIdx.x == 0 && threadIdx.x < E_EXP) {
        g_cnt[threadIdx.x]  = 0;
        g_top1[threadIdx.x] = 0;
        g_psum[threadIdx.x] = 0.0f;
    }
}

// ---------------------------------------------------------------------------
__global__ void gate_kernel(const float* __restrict__ x,
                            const float* __restrict__ Wg,
                            const float* __restrict__ bg) {
    int t = blockIdx.x;
    int w = threadIdx.x >> 5;
    int lane = threadIdx.x & 31;
    const float* xr = x + (size_t)t * D_DIM;

    float s = 0.0f;
    for (int d = lane; d < D_DIM; d += 32)
        s += xr[d] * Wg[d * E_EXP + w];
    #pragma unroll
    for (int o = 16; o; o >>= 1) s += __shfl_xor_sync(0xffffffffu, s, o);

    __shared__ float lg[E_EXP];
    if (lane == 0) lg[w] = s + bg[w];
    __syncthreads();

    if (threadIdx.x == 0) {
        float mx = lg[0];
        #pragma unroll
        for (int e = 1; e < E_EXP; e++) mx = fmaxf(mx, lg[e]);
        float p[E_EXP];
        float sum = 0.0f;
        #pragma unroll
        for (int e = 0; e < E_EXP; e++) { p[e] = __expf(lg[e] - mx); sum += p[e]; }
        float inv = 1.0f / sum;
        #pragma unroll
        for (int e = 0; e < E_EXP; e++) { p[e] *= inv; atomicAdd(&g_psum[e], p[e]); }

        int i0 = 0;
        #pragma unroll
        for (int e = 1; e < E_EXP; e++) if (p[e] > p[i0]) i0 = e;
        int i1 = -1;
        #pragma unroll
        for (int e = 0; e < E_EXP; e++) {
            if (e == i0) continue;
            if (i1 < 0 || p[e] > p[i1]) i1 = e;
        }
        atomicAdd(&g_top1[i0], 1);

        int pos0 = atomicAdd(&g_cnt[i0], 1);
        g_list[i0 * T_TOK + pos0] = t * 2 + 0;
        g_wts[t * 2 + 0] = p[i0];
        int pos1 = atomicAdd(&g_cnt[i1], 1);
        g_list[i1 * T_TOK + pos1] = t * 2 + 1;
        g_wts[t * 2 + 1] = p[i1];
    }
}

// ---------------------------------------------------------------------------
__global__ void aux_kernel(float* out, int out_size) {
    if (threadIdx.x == 0 && blockIdx.x == 0) {
        float aux = 0.0f;
        #pragma unroll
        for (int e = 0; e < E_EXP; e++)
            aux += ((float)g_top1[e] / ((float)T_TOK + 1e-8f)) *
                   (g_psum[e] / (float)T_TOK);
        aux *= (float)E_EXP;
        if (out_size > T_TOK * D_DIM) out[T_TOK * D_DIM] = aux;
    }
}

// ---------------------------------------------------------------------------
__device__ __forceinline__ void mma16816(float* d, const uint32_t* a, const uint32_t* b) {
    asm volatile("mma.sync.aligned.m16n8k16.row.col.f32.bf16.bf16.f32 "
                 "{%0,%1,%2,%3}, {%4,%5,%6,%7}, {%8,%9}, {%0,%1,%2,%3};\n"
                 : "+f"(d[0]), "+f"(d[1]), "+f"(d[2]), "+f"(d[3])
                 : "r"(a[0]), "r"(a[1]), "r"(a[2]), "r"(a[3]), "r"(b[0]), "r"(b[1]));
}

__device__ __forceinline__ void split_bf16(float v, __nv_bfloat16& hi, __nv_bfloat16& lo) {
    hi = __float2bfloat16(v);
    lo = __float2bfloat16(v - __bfloat162float(hi));
}

// ---------------------------------------------------------------------------
// GEMM1 (tensor core, in-kernel hi/lo split from ORIGINAL fp32 tensors):
// g_h[entry][f] = relu( x[token] @ W1[e] + b1[e] ),  fp32 output.
__global__ __launch_bounds__(256)
void gemm1_tc_kernel(const float* __restrict__ x,
                     const float* __restrict__ W1,
                     const float* __restrict__ b1) {
    int e = blockIdx.z;
    int n = g_cnt[e];
    int m0 = blockIdx.x * BM;
    if (m0 >= n) return;
    int n0 = blockIdx.y * BN;

    __shared__ int rows_s[BM];
    __shared__ __align__(16) __nv_bfloat16 Ahi[BM * ASTRIDE];
    __shared__ __align__(16) __nv_bfloat16 Alo[BM * ASTRIDE];
    __shared__ __align__(16) __nv_bfloat16 Bhi[BN * ASTRIDE];
    __shared__ __align__(16) __nv_bfloat16 Blo[BN * ASTRIDE];

    int tid = threadIdx.x;
    if (tid < BM) {
        int r = m0 + tid;
        rows_s[tid] = (r < n) ? g_list[e * T_TOK + r] : g_list[e * T_TOK];
    }
    __syncthreads();

    // A loader: each thread owns row ar, 16-wide k-chunk ak
    int ar = tid >> 1, ak = (tid & 1) * 16;
    const float* pa = x + (size_t)(rows_s[ar] >> 1) * D_DIM + ak;
    // B loader: thread covers k = bk + 8q, 4 consecutive n at bn
    int bk = tid >> 5;             // 0..7
    int bn = (tid & 31) * 4;       // 0..124
    const float* Wb = W1 + (size_t)e * D_DIM * F_DIM;

    int lane = tid & 31, warp = tid >> 5;
    int wm = (warp & 1) * 64, wn = (warp >> 1) * 32;
    int g = lane >> 2, tig = lane & 3;

    float acc[4][4][4] = {};

    for (int kk = 0; kk < D_DIM; kk += BKS) {
        __syncthreads();
        // ---- A tile: 128m x 32k, split hi/lo
        #pragma unroll
        for (int j = 0; j < 16; j += 4) {
            float4 v = *(const float4*)(pa + kk + j);
            float vs[4] = {v.x, v.y, v.z, v.w};
            #pragma unroll
            for (int q = 0; q < 4; q++) {
                __nv_bfloat16 hi, lo;
                split_bf16(vs[q], hi, lo);
                Ahi[ar * ASTRIDE + ak + j + q] = hi;
                Alo[ar * ASTRIDE + ak + j + q] = lo;
            }
        }
        // ---- B tile: W1[kk..kk+31][n0..n0+127] -> transposed [n][k], split
        #pragma unroll
        for (int kq = 0; kq < 4; kq++) {
            int k = bk + kq * 8;
            float4 w = *(const float4*)(Wb + (size_t)(kk + k) * F_DIM + n0 + bn);
            float vs[4] = {w.x, w.y, w.z, w.w};
            #pragma unroll
            for (int q = 0; q < 4; q++) {
                __nv_bfloat16 hi, lo;
                split_bf16(vs[q], hi, lo);
                Bhi[(bn + q) * ASTRIDE + k] = hi;
                Blo[(bn + q) * ASTRIDE + k] = lo;
            }
        }
        __syncthreads();

        #pragma unroll
        for (int ks = 0; ks < 2; ks++) {
            int kb = ks * 16;
            uint32_t ah[4][4], bh[4][2], bx[4][2];
            // A-hi fragments
            #pragma unroll
            for (int mi = 0; mi < 4; mi++) {
                const __nv_bfloat16* p = Ahi + (wm + mi * 16 + g) * ASTRIDE + kb + tig * 2;
                ah[mi][0] = *(const uint32_t*)p;
                ah[mi][1] = *(const uint32_t*)(p + 8 * ASTRIDE);
                ah[mi][2] = *(const uint32_t*)(p + 8);
                ah[mi][3] = *(const uint32_t*)(p + 8 * ASTRIDE + 8);
            }
            // B-hi fragments
            #pragma unroll
            for (int nj = 0; nj < 4; nj++) {
                const __nv_bfloat16* p = Bhi + (wn + nj * 8 + g) * ASTRIDE + kb + tig * 2;
                bh[nj][0] = *(const uint32_t*)p;
                bh[nj][1] = *(const uint32_t*)(p + 8);
            }
            // hi * hi
            #pragma unroll
            for (int mi = 0; mi < 4; mi++)
                #pragma unroll
                for (int nj = 0; nj < 4; nj++)
                    mma16816(acc[mi][nj], ah[mi], bh[nj]);
            // B-lo fragments; hi * lo
            #pragma unroll
            for (int nj = 0; nj < 4; nj++) {
                const __nv_bfloat16* p = Blo + (wn + nj * 8 + g) * ASTRIDE + kb + tig * 2;
                bx[nj][0] = *(const uint32_t*)p;
                bx[nj][1] = *(const uint32_t*)(p + 8);
            }
            #pragma unroll
            for (int mi = 0; mi < 4; mi++)
                #pragma unroll
                for (int nj = 0; nj < 4; nj++)
                    mma16816(acc[mi][nj], ah[mi], bx[nj]);
            // A-lo fragments (reuse ah regs); lo * hi
            #pragma unroll
            for (int mi = 0; mi < 4; mi++) {
                const __nv_bfloat16* p = Alo + (wm + mi * 16 + g) * ASTRIDE + kb + tig * 2;
                ah[mi][0] = *(const uint32_t*)p;
                ah[mi][1] = *(const uint32_t*)(p + 8 * ASTRIDE);
                ah[mi][2] = *(const uint32_t*)(p + 8);
                ah[mi][3] = *(const uint32_t*)(p + 8 * ASTRIDE + 8);
            }
            #pragma unroll
            for (int mi = 0; mi < 4; mi++)
                #pragma unroll
                for (int nj = 0; nj < 4; nj++)
                    mma16816(acc[mi][nj], ah[mi], bh[nj]);
        }
    }

    // Epilogue: relu + bias -> g_h fp32 (indexed by entry)
    const float* b1g = b1 + (size_t)e * F_DIM;
    #pragma unroll
    for (int mi = 0; mi < 4; mi++) {
        #pragma unroll
        for (int half = 0; half < 2; half++) {
            int rl = wm + mi * 16 + g + half * 8;
            if (m0 + rl >= n) continue;
            int entry = rows_s[rl];
            float* hrow = g_h + (size_t)entry * F_DIM;
            #pragma unroll
            for (int ni = 0; ni < 4; ni++) {
                int col = n0 + wn + ni * 8 + tig * 2;
                hrow[col]     = fmaxf(acc[mi][ni][half * 2 + 0] + b1g[col], 0.0f);
                hrow[col + 1] = fmaxf(acc[mi][ni][half * 2 + 1] + b1g[col + 1], 0.0f);
            }
        }
    }
}

// ---------------------------------------------------------------------------
// GEMM2: round-1 verified SIMT fp32. y = h @ W2[e] + b2; out += wt*y.
__global__ __launch_bounds__(256)
void gemm2_kernel(const float* __restrict__ W2,
                  const float* __restrict__ b2,
                  float* __restrict__ out) {
    int e = blockIdx.z;
    int n = g_cnt[e];
    int m0 = blockIdx.x * SBM;
    if (m0 >= n) return;
    int d0 = blockIdx.y * SBN;

    __shared__ float As[SBK][SBM];
    __shared__ float Bs[SBK][SBN];

    int tid = threadIdx.x;
    int tx = tid & 15, ty = tid >> 4;

    int lr = tid >> 2;
    int lc = (tid & 3) * 4;
    const float* arow = nullptr;
    if (m0 + lr < n) {
        int entry = g_list[e * T_TOK + m0 + lr];
        arow = g_h + (size_t)entry * F_DIM;
    }
    int brow = tid >> 4;
    int bcol = (tid & 15) * 4;
    const float* Bbase = W2 + (size_t)e * F_DIM * D_DIM + d0;

    float acc[4][4] = {};
    for (int kk = 0; kk < F_DIM; kk += SBK) {
        float4 av = make_float4(0.f, 0.f, 0.f, 0.f);
        if (arow) av = *(const float4*)(arow + kk + lc);
        As[lc + 0][lr] = av.x; As[lc + 1][lr] = av.y;
        As[lc + 2][lr] = av.z; As[lc + 3][lr] = av.w;
        *(float4*)&Bs[brow][bcol] =
            *(const float4*)(Bbase + (size_t)(kk + brow) * D_DIM + bcol);
        __syncthreads();
        #pragma unroll
        for (int k = 0; k < SBK; k++) {
            float4 a = *(const float4*)&As[k][ty * 4];
            float4 b = *(const float4*)&Bs[k][tx * 4];
            float ar[4] = {a.x, a.y, a.z, a.w};
            float br[4] = {b.x, b.y, b.z, b.w};
            #pragma unroll
            for (int i = 0; i < 4; i++)
                #pragma unroll
                for (int j = 0; j < 4; j++)
                    acc[i][j] = fmaf(ar[i], br[j], acc[i][j]);
        }
        __syncthreads();
    }

    #pragma unroll
    for (int i = 0; i < 4; i++) {
        int r = m0 + ty * 4 + i;
        if (r >= n) continue;
        int entry = g_list[e * T_TOK + r];
        int t = entry >> 1;
        float wt = g_wts[entry];
        float* orow = out + (size_t)t * D_DIM + d0 + tx * 4;
        #pragma unroll
        for (int j = 0; j < 4; j++) {
            float v = acc[i][j] + b2[e * D_DIM + d0 + tx * 4 + j];
            atomicAdd(&orow[j], wt * v);
        }
    }
}

// ---------------------------------------------------------------------------
extern "C" void kernel_launch(void* const* d_in, const int* in_sizes, int n_in,
                              void* d_out, int out_size) {
    const float* x  = (const float*)d_in[0];
    const float* Wg = (const float*)d_in[1];
    const float* bg = (const float*)d_in[2];
    const float* W1 = (const float*)d_in[3];
    const float* b1 = (const float*)d_in[4];
    const float* W2 = (const float*)d_in[5];
    const float* b2 = (const float*)d_in[6];
    float* out = (float*)d_out;

    zero_kernel<<<256, 256>>>(out, out_size);
    gate_kernel<<<T_TOK, 256>>>(x, Wg, bg);
    aux_kernel<<<1, 32>>>(out, out_size);

    dim3 g1(T_TOK / BM, F_DIM / BN, E_EXP);      // (16, 32, 8), early-exit on m
    gemm1_tc_kernel<<<g1, 256>>>(x, W1, b1);

    dim3 g2(T_TOK / SBM, D_DIM / SBN, E_EXP);    // (32, 16, 8)
    gemm2_kernel<<<g2, 256>>>(W2, b2, out);
}

// round 7
// speedup vs baseline: 2.3645x; 2.3645x over previous
#include <cuda_runtime.h>
#include <cuda_bf16.h>
#include <math.h>
#include <stdint.h>

// Problem constants
#define T_TOK 2048
#define D_DIM 1024
#define F_DIM 4096
#define E_EXP 8
#define K_TOP 2
#define NENT  (T_TOK * K_TOP)

// TC tiling
#define BM 128
#define BN 128
#define BKS 16
#define AST 20          // A smem row stride (floats); 80B, 16B-aligned rows
#define BST 132         // B smem row stride (floats); 528B, 16B-aligned rows
#define A_ELE (BM * AST)
#define B_ELE (BKS * BST)

// ---------------------------------------------------------------------------
// Scratch
__device__ float g_h[(size_t)NENT * F_DIM];   // 64 MB fp32
__device__ int   g_list[E_EXP * T_TOK];
__device__ float g_wts[NENT];
__device__ int   g_cnt[E_EXP];
__device__ int   g_top1[E_EXP];
__device__ float g_psum[E_EXP];

// ---------------------------------------------------------------------------
__global__ void zero_kernel(float* out, int out_size) {
    int stride = gridDim.x * blockDim.x;
    for (int i = blockIdx.x * blockDim.x + threadIdx.x; i < out_size; i += stride)
        out[i] = 0.0f;
    if (blockIdx.x == 0 && threadIdx.x < E_EXP) {
        g_cnt[threadIdx.x]  = 0;
        g_top1[threadIdx.x] = 0;
        g_psum[threadIdx.x] = 0.0f;
    }
}

// ---------------------------------------------------------------------------
__global__ void gate_kernel(const float* __restrict__ x,
                            const float* __restrict__ Wg,
                            const float* __restrict__ bg) {
    int t = blockIdx.x;
    int w = threadIdx.x >> 5;
    int lane = threadIdx.x & 31;
    const float* xr = x + (size_t)t * D_DIM;

    float s = 0.0f;
    for (int d = lane; d < D_DIM; d += 32)
        s += xr[d] * Wg[d * E_EXP + w];
    #pragma unroll
    for (int o = 16; o; o >>= 1) s += __shfl_xor_sync(0xffffffffu, s, o);

    __shared__ float lg[E_EXP];
    if (lane == 0) lg[w] = s + bg[w];
    __syncthreads();

    if (threadIdx.x == 0) {
        float mx = lg[0];
        #pragma unroll
        for (int e = 1; e < E_EXP; e++) mx = fmaxf(mx, lg[e]);
        float p[E_EXP];
        float sum = 0.0f;
        #pragma unroll
        for (int e = 0; e < E_EXP; e++) { p[e] = __expf(lg[e] - mx); sum += p[e]; }
        float inv = 1.0f / sum;
        #pragma unroll
        for (int e = 0; e < E_EXP; e++) { p[e] *= inv; atomicAdd(&g_psum[e], p[e]); }

        int i0 = 0;
        #pragma unroll
        for (int e = 1; e < E_EXP; e++) if (p[e] > p[i0]) i0 = e;
        int i1 = -1;
        #pragma unroll
        for (int e = 0; e < E_EXP; e++) {
            if (e == i0) continue;
            if (i1 < 0 || p[e] > p[i1]) i1 = e;
        }
        atomicAdd(&g_top1[i0], 1);

        int pos0 = atomicAdd(&g_cnt[i0], 1);
        g_list[i0 * T_TOK + pos0] = t * 2 + 0;
        g_wts[t * 2 + 0] = p[i0];
        int pos1 = atomicAdd(&g_cnt[i1], 1);
        g_list[i1 * T_TOK + pos1] = t * 2 + 1;
        g_wts[t * 2 + 1] = p[i1];
    }
}

// ---------------------------------------------------------------------------
__global__ void aux_kernel(float* out, int out_size) {
    if (threadIdx.x == 0 && blockIdx.x == 0) {
        float aux = 0.0f;
        #pragma unroll
        for (int e = 0; e < E_EXP; e++)
            aux += ((float)g_top1[e] / ((float)T_TOK + 1e-8f)) *
                   (g_psum[e] / (float)T_TOK);
        aux *= (float)E_EXP;
        if (out_size > T_TOK * D_DIM) out[T_TOK * D_DIM] = aux;
    }
}

// ---------------------------------------------------------------------------
__device__ __forceinline__ void mma16816(float* d, const uint32_t* a, const uint32_t* b) {
    asm volatile("mma.sync.aligned.m16n8k16.row.col.f32.bf16.bf16.f32 "
                 "{%0,%1,%2,%3}, {%4,%5,%6,%7}, {%8,%9}, {%0,%1,%2,%3};\n"
                 : "+f"(d[0]), "+f"(d[1]), "+f"(d[2]), "+f"(d[3])
                 : "r"(a[0]), "r"(a[1]), "r"(a[2]), "r"(a[3]), "r"(b[0]), "r"(b[1]));
}

__device__ __forceinline__ void cp16(unsigned sdst, const void* gsrc) {
    asm volatile("cp.async.cg.shared.global [%0], [%1], 16;\n" :: "r"(sdst), "l"(gsrc));
}
__device__ __forceinline__ void cp_commit() { asm volatile("cp.async.commit_group;\n" ::: "memory"); }
template <int N>
__device__ __forceinline__ void cp_wait() { asm volatile("cp.async.wait_group %0;\n" :: "n"(N) : "memory"); }

// split two floats -> packed bf16x2 hi + packed bf16x2 lo (low half = first arg)
__device__ __forceinline__ void split2(float f0, float f1, uint32_t& hi, uint32_t& lo) {
    __nv_bfloat162 h = __floats2bfloat162_rn(f0, f1);
    float h0 = __bfloat162float(h.x), h1 = __bfloat162float(h.y);
    __nv_bfloat162 l = __floats2bfloat162_rn(f0 - h0, f1 - h1);
    hi = *(uint32_t*)&h;
    lo = *(uint32_t*)&l;
}

// ---------------------------------------------------------------------------
// Shared TC core. A rows gathered (per-thread base ptr pa, stride = KDIM),
// B = weights [k][n] row-major (bbase = &W[e][0][n0], row stride NDIM).
// acc laid out exactly as round-6 (proven): warp 64x32, acc[4][4][4].
template <int KDIM, int NDIM>
__device__ __forceinline__ void tc_core(
    const float* pa,                 // this thread's A row base (row = tid>>1)
    const float* bbase,              // W + e*K*N + n0
    float* Afp, float* Bfp,          // smem: Afp[2][A_ELE], Bfp[2][B_ELE]
    int tid, float acc[4][4][4])
{
    // A loader: row = tid>>1, two 16B chunks at float offset (tid&1)*8 + {0,4}
    int arow = tid >> 1, afo = (tid & 1) * 8;
    unsigned aS = (unsigned)__cvta_generic_to_shared(Afp);
    unsigned bS = (unsigned)__cvta_generic_to_shared(Bfp);
    unsigned adst = aS + (arow * AST + afo) * 4;
    // B loader: krow = tid>>4, cols (tid&15)*4 + j*64
    int bkr = tid >> 4, bc = (tid & 15) * 4;
    unsigned bdst = bS + (bkr * BST + bc) * 4;

    int lane = tid & 31, warp = tid >> 5;
    int wm = (warp & 1) * 64, wn = (warp >> 1) * 32;
    int g = lane >> 2, tig = lane & 3;

    const int NS = KDIM / BKS;

    // preload slab 0 into buf 0
    cp16(adst, pa + afo);
    cp16(adst + 16, pa + afo + 4);
    cp16(bdst, bbase + (size_t)bkr * NDIM + bc);
    cp16(bdst + 256, bbase + (size_t)bkr * NDIM + bc + 64);
    cp_commit();

    for (int s = 0; s < NS; s++) {
        int buf = s & 1;
        if (s + 1 < NS) {
            int kk = (s + 1) * BKS;
            unsigned bo = (buf ^ 1);
            cp16(adst + bo * A_ELE * 4, pa + kk + afo);
            cp16(adst + bo * A_ELE * 4 + 16, pa + kk + afo + 4);
            const float* bsrc = bbase + (size_t)(kk + bkr) * NDIM + bc;
            cp16(bdst + bo * B_ELE * 4, bsrc);
            cp16(bdst + bo * B_ELE * 4 + 256, bsrc + 64);
            cp_commit();
            cp_wait<1>();
        } else {
            cp_wait<0>();
        }
        __syncthreads();

        const float* Ab = Afp + buf * A_ELE;
        const float* Bb = Bfp + buf * B_ELE;

        // Build A fragments (hi+lo) for this k16 slab
        uint32_t ah[4][4], al[4][4];
        #pragma unroll
        for (int mi = 0; mi < 4; mi++) {
            const float* p = Ab + (wm + mi * 16 + g) * AST + tig * 2;
            float2 v0 = *(const float2*)p;                 // (m=g,   k=2tig)
            float2 v1 = *(const float2*)(p + 8 * AST);     // (m=g+8, k=2tig)
            float2 v2 = *(const float2*)(p + 8);           // (m=g,   k=2tig+8)
            float2 v3 = *(const float2*)(p + 8 * AST + 8);
            split2(v0.x, v0.y, ah[mi][0], al[mi][0]);
            split2(v1.x, v1.y, ah[mi][1], al[mi][1]);
            split2(v2.x, v2.y, ah[mi][2], al[mi][2]);
            split2(v3.x, v3.y, ah[mi][3], al[mi][3]);
        }
        // B per nj: build frags, run 3 split-products
        #pragma unroll
        for (int nj = 0; nj < 4; nj++) {
            int nn = wn + nj * 8 + g;
            const float* p = Bb + (2 * tig) * BST + nn;
            uint32_t bh[2], bl[2];
            split2(p[0], p[BST], bh[0], bl[0]);            // k=2tig, 2tig+1
            split2(p[8 * BST], p[9 * BST], bh[1], bl[1]);  // k=2tig+8, +9
            #pragma unroll
            for (int mi = 0; mi < 4; mi++) {
                mma16816(acc[mi][nj], ah[mi], bh);         // hi*hi
                mma16816(acc[mi][nj], ah[mi], bl);         // hi*lo
                mma16816(acc[mi][nj], al[mi], bh);         // lo*hi
            }
        }
        __syncthreads();
    }
}

// ---------------------------------------------------------------------------
// GEMM1: g_h[entry][f] = relu( x[token] @ W1[e] + b1[e] )
__global__ __launch_bounds__(256, 2)
void gemm1_tc_kernel(const float* __restrict__ x,
                     const float* __restrict__ W1,
                     const float* __restrict__ b1) {
    int e = blockIdx.z;
    int n = g_cnt[e];
    int m0 = blockIdx.x * BM;
    if (m0 >= n) return;
    int n0 = blockIdx.y * BN;

    __shared__ int rows_s[BM];
    __shared__ __align__(16) float Afp[2 * A_ELE];
    __shared__ __align__(16) float Bfp[2 * B_ELE];

    int tid = threadIdx.x;
    if (tid < BM) {
        int r = m0 + tid;
        rows_s[tid] = (r < n) ? g_list[e * T_TOK + r] : g_list[e * T_TOK];
    }
    __syncthreads();

    const float* pa = x + (size_t)(rows_s[tid >> 1] >> 1) * D_DIM;
    const float* bbase = W1 + (size_t)e * D_DIM * F_DIM + n0;

    float acc[4][4][4] = {};
    tc_core<D_DIM, F_DIM>(pa, bbase, Afp, Bfp, tid, acc);

    int lane = tid & 31, warp = tid >> 5;
    int wm = (warp & 1) * 64, wn = (warp >> 1) * 32;
    int g = lane >> 2, tig = lane & 3;
    const float* b1g = b1 + (size_t)e * F_DIM;
    #pragma unroll
    for (int mi = 0; mi < 4; mi++) {
        #pragma unroll
        for (int half = 0; half < 2; half++) {
            int rl = wm + mi * 16 + g + half * 8;
            if (m0 + rl >= n) continue;
            int entry = rows_s[rl];
            float* hrow = g_h + (size_t)entry * F_DIM;
            #pragma unroll
            for (int ni = 0; ni < 4; ni++) {
                int col = n0 + wn + ni * 8 + tig * 2;
                hrow[col]     = fmaxf(acc[mi][ni][half * 2 + 0] + b1g[col], 0.0f);
                hrow[col + 1] = fmaxf(acc[mi][ni][half * 2 + 1] + b1g[col + 1], 0.0f);
            }
        }
    }
}

// ---------------------------------------------------------------------------
// GEMM2: out[t] += wt * ( g_h[entry] @ W2[e] + b2[e] )
__global__ __launch_bounds__(256, 2)
void gemm2_tc_kernel(const float* __restrict__ W2,
                     const float* __restrict__ b2,
                     float* __restrict__ out) {
    int e = blockIdx.z;
    int n = g_cnt[e];
    int m0 = blockIdx.x * BM;
    if (m0 >= n) return;
    int n0 = blockIdx.y * BN;

    __shared__ int rows_s[BM];
    __shared__ __align__(16) float Afp[2 * A_ELE];
    __shared__ __align__(16) float Bfp[2 * B_ELE];

    int tid = threadIdx.x;
    if (tid < BM) {
        int r = m0 + tid;
        rows_s[tid] = (r < n) ? g_list[e * T_TOK + r] : g_list[e * T_TOK];
    }
    __syncthreads();

    const float* pa = g_h + (size_t)rows_s[tid >> 1] * F_DIM;
    const float* bbase = W2 + (size_t)e * F_DIM * D_DIM + n0;

    float acc[4][4][4] = {};
    tc_core<F_DIM, D_DIM>(pa, bbase, Afp, Bfp, tid, acc);

    int lane = tid & 31, warp = tid >> 5;
    int wm = (warp & 1) * 64, wn = (warp >> 1) * 32;
    int g = lane >> 2, tig = lane & 3;
    const float* b2g = b2 + (size_t)e * D_DIM;
    #pragma unroll
    for (int mi = 0; mi < 4; mi++) {
        #pragma unroll
        for (int half = 0; half < 2; half++) {
            int rl = wm + mi * 16 + g + half * 8;
            if (m0 + rl >= n) continue;
            int entry = rows_s[rl];
            int t = entry >> 1;
            float wt = g_wts[entry];
            float* orow = out + (size_t)t * D_DIM;
            #pragma unroll
            for (int ni = 0; ni < 4; ni++) {
                int col = n0 + wn + ni * 8 + tig * 2;
                float v0 = (acc[mi][ni][half * 2 + 0] + b2g[col]) * wt;
                float v1 = (acc[mi][ni][half * 2 + 1] + b2g[col + 1]) * wt;
                atomicAdd(&orow[col], v0);
                atomicAdd(&orow[col + 1], v1);
            }
        }
    }
}

// ---------------------------------------------------------------------------
extern "C" void kernel_launch(void* const* d_in, const int* in_sizes, int n_in,
                              void* d_out, int out_size) {
    const float* x  = (const float*)d_in[0];
    const float* Wg = (const float*)d_in[1];
    const float* bg = (const float*)d_in[2];
    const float* W1 = (const float*)d_in[3];
    const float* b1 = (const float*)d_in[4];
    const float* W2 = (const float*)d_in[5];
    const float* b2 = (const float*)d_in[6];
    float* out = (float*)d_out;

    zero_kernel<<<256, 256>>>(out, out_size);
    gate_kernel<<<T_TOK, 256>>>(x, Wg, bg);
    aux_kernel<<<1, 32>>>(out, out_size);

    dim3 g1(T_TOK / BM, F_DIM / BN, E_EXP);      // (16, 32, 8)
    gemm1_tc_kernel<<<g1, 256>>>(x, W1, b1);

    dim3 g2(T_TOK / BM, D_DIM / BN, E_EXP);      // (16, 8, 8)
    gemm2_tc_kernel<<<g2, 256>>>(W2, b2, out);
}